// round 16
// baseline (speedup 1.0000x reference)
#include <cuda_runtime.h>
#include <cuda_fp16.h>
#include <cstdint>

#define N_NODES 8192
#define FIN 256
#define FOUT 64
#define LOG2E 1.4426950408889634f
#define NEG10L2E (-14.426950408889634f)

// ---- k_mma geometry (R12-proven shape) ----
#define TM 128
#define TKJ 64
#define JSPLIT 16
#define KCHUNK (N_NODES / JSPLIT)    // 512
#define NT (KCHUNK / TKJ)            // 8

// dynamic smem layout for k_mma
#define BS_BYTES (8 * 16 * 68 * 8)         // 69632
#define SMEM_MMA (BS_BYTES + KCHUNK * 4)   // 71680

// ---- scratch (allocation-free rule) ----
__device__ float g_s1[N_NODES];                    // prescaled by LOG2E
__device__ float g_s2[N_NODES];                    // prescaled by LOG2E
__device__ uint2 g_hp[(N_NODES / 16) * 256];       // fragment-packed fp16 h, 1 MB
__device__ __half g_parth[JSPLIT][N_NODES][FOUT];  // fp16 partials, 16 MB
__device__ float g_lpart[JSPLIT][N_NODES];         // 512 KB
__device__ unsigned g_s2key = 0u;                  // ordered-key max of s2' (idempotent)

__device__ __forceinline__ unsigned fenc(float f) {
    unsigned u = __float_as_uint(f);
    return u ^ ((unsigned)((int)u >> 31) | 0x80000000u);
}
__device__ __forceinline__ float fdec(unsigned u) {
    unsigned b = (u & 0x80000000u) ? (u ^ 0x80000000u) : ~u;
    return __uint_as_float(b);
}
__device__ __forceinline__ float ex2(float x) {
    float r;
    asm("ex2.approx.f32 %0, %1;" : "=f"(r) : "f"(x));
    return r;
}
__device__ __forceinline__ uint32_t packh2(float lo, float hi) {
    uint32_t r;
    asm("cvt.rn.f16x2.f32 %0, %1, %2;" : "=r"(r) : "f"(hi), "f"(lo));
    return r;
}
__device__ __forceinline__ void mma_fp16(float c[4],
    uint32_t a0, uint32_t a1, uint32_t a2, uint32_t a3,
    uint32_t b0, uint32_t b1)
{
    asm volatile(
        "mma.sync.aligned.m16n8k16.row.col.f32.f16.f16.f32 "
        "{%0,%1,%2,%3}, {%4,%5,%6,%7}, {%8,%9}, {%0,%1,%2,%3};"
        : "+f"(c[0]), "+f"(c[1]), "+f"(c[2]), "+f"(c[3])
        : "r"(a0), "r"(a1), "r"(a2), "r"(a3), "r"(b0), "r"(b1));
}
// weight in log2 domain: lrelu2 - m2 folded into per-row consts
__device__ __forceinline__ float wgt(float s1a, float s1b, float mc,
                                     float s2, int av) {
    const float t1 = s1a + s2;
    const float t2 = fmaf(0.2f, s2, s1b);
    float y = fmaxf(t1, t2);
    y = (av > 0) ? y : mc;
    return ex2(y);
}

// ============================================================================
// Kernel 1: h = input @ W (64-row tiles, register-prefetched chunks); emit
// prescaled s1,s2, s2'-max, pi-permuted fp16 B. Grid: 128 blocks, 512 thr.
// ============================================================================
__global__ __launch_bounds__(512) void k_h(
    const float* __restrict__ input,   // [N, FIN]
    const float* __restrict__ W,       // [FIN, FOUT]
    const float* __restrict__ a)       // [2*FOUT]
{
    __shared__ float pool[8192];       // in_s[64][64] @0 | w_s[64][64] @4096
    const int t = threadIdx.x;         // 0..511
    const int i0 = blockIdx.x * 64;
    const int f4 = (t & 15) * 4;
    const int i2 = (t >> 4) * 2;       // 2 rows per thread

    const float4* in4 = reinterpret_cast<const float4*>(input);
    const float4* W4  = reinterpret_cast<const float4*>(W);

    float4 pin[2], pw[2];
    const int ldrow0 = t >> 4, ldc0 = t & 15;
    const int ldrow1 = (t + 512) >> 4, ldc1 = (t + 512) & 15;

    pin[0] = in4[(size_t)(i0 + ldrow0) * 64 + ldc0];
    pin[1] = in4[(size_t)(i0 + ldrow1) * 64 + ldc1];
    pw[0]  = W4[(size_t)ldrow0 * 16 + ldc0];
    pw[1]  = W4[(size_t)ldrow1 * 16 + ldc1];

    float c[2][4];
    #pragma unroll
    for (int r = 0; r < 2; ++r) { c[r][0]=0.f; c[r][1]=0.f; c[r][2]=0.f; c[r][3]=0.f; }

    for (int kc = 0; kc < 4; ++kc) {
        __syncthreads();
        *reinterpret_cast<float4*>(&pool[ldrow0 * 64 + ldc0 * 4]) = pin[0];
        *reinterpret_cast<float4*>(&pool[ldrow1 * 64 + ldc1 * 4]) = pin[1];
        *reinterpret_cast<float4*>(&pool[4096 + ldrow0 * 64 + ldc0 * 4]) = pw[0];
        *reinterpret_cast<float4*>(&pool[4096 + ldrow1 * 64 + ldc1 * 4]) = pw[1];
        __syncthreads();

        if (kc < 3) {
            pin[0] = in4[(size_t)(i0 + ldrow0) * 64 + (kc + 1) * 16 + ldc0];
            pin[1] = in4[(size_t)(i0 + ldrow1) * 64 + (kc + 1) * 16 + ldc1];
            pw[0]  = W4[(size_t)((kc + 1) * 64 + ldrow0) * 16 + ldc0];
            pw[1]  = W4[(size_t)((kc + 1) * 64 + ldrow1) * 16 + ldc1];
        }

        #pragma unroll 8
        for (int kk = 0; kk < 64; ++kk) {
            const float4 wv = *reinterpret_cast<const float4*>(&pool[4096 + kk * 64 + f4]);
            #pragma unroll
            for (int r = 0; r < 2; ++r) {
                const float iv = pool[(i2 + r) * 64 + kk];
                c[r][0] = fmaf(iv, wv.x, c[r][0]);
                c[r][1] = fmaf(iv, wv.y, c[r][1]);
                c[r][2] = fmaf(iv, wv.z, c[r][2]);
                c[r][3] = fmaf(iv, wv.w, c[r][3]);
            }
        }
    }

    // stage fp32 h into padded smem h_s[64][65]
    __syncthreads();
    #pragma unroll
    for (int r = 0; r < 2; ++r) {
        float* row = &pool[(i2 + r) * 65 + f4];
        row[0] = c[r][0]; row[1] = c[r][1]; row[2] = c[r][2]; row[3] = c[r][3];
    }
    __syncthreads();

    // s1 / s2 (exact fp32), prescaled by log2(e); chip-wide max of s2'
    if (t < 64) {
        float s1 = 0.f, s2 = 0.f;
        #pragma unroll 8
        for (int f = 0; f < 64; ++f) {
            const float hv = pool[t * 65 + f];
            s1 = fmaf(hv, __ldg(&a[f]), s1);
            s2 = fmaf(hv, __ldg(&a[64 + f]), s2);
        }
        g_s1[i0 + t] = s1 * LOG2E;
        const float s2p = s2 * LOG2E;
        g_s2[i0 + t] = s2p;
        float m = s2p;
        #pragma unroll
        for (int d = 16; d; d >>= 1)
            m = fmaxf(m, __shfl_xor_sync(0xffffffffu, m, d));
        if ((t & 31) == 0) atomicMax(&g_s2key, fenc(m));
    }

    // pi-permuted fragment-packed fp16 h:
    // per 16-row block, entry (q,f): .x=(h[4q],h[4q+1]), .y=(h[4q+2],h[4q+3])
    #pragma unroll
    for (int e = 0; e < 2; ++e) {
        const int idx = t + e * 512;        // 0..1023
        const int blk = idx >> 8;           // 0..3
        const int q   = (idx >> 6) & 3;
        const int f   = idx & 63;
        const int rb  = blk * 16 + 4 * q;
        uint2 v;
        v.x = packh2(pool[(rb + 0) * 65 + f], pool[(rb + 1) * 65 + f]);
        v.y = packh2(pool[(rb + 2) * 65 + f], pool[(rb + 3) * 65 + f]);
        g_hp[((i0 >> 4) + blk) * 256 + q * 64 + f] = v;
    }
}

// ============================================================================
// Kernel 2: fused fp16 HMMA GEMM — whole 8-tile B chunk staged once,
// barrier-free mainloop, ROTATING adj prefetch (consume av[ks], immediately
// overwrite with tile t+1's load: ~3/4-tile latency slack, zero extra regs).
// fp16 partial outputs. Grid (64, 16), 256 thr, occ 2.
// ============================================================================
__global__ __launch_bounds__(256, 2) void k_mma(const int* __restrict__ adj)
{
    extern __shared__ __align__(16) char smem[];
    uint2 (*Bs)[16][68] = reinterpret_cast<uint2 (*)[16][68]>(smem);   // [8][16][68]
    float* s2s = reinterpret_cast<float*>(smem + BS_BYTES);            // [512]

    const int t = threadIdx.x;
    const int w = t >> 5;
    const int l = t & 31;
    const int gid = l >> 2;
    const int tig = l & 3;
    const int i0 = blockIdx.x * TM;
    const int js = blockIdx.y;
    const int j0 = js * KCHUNK;
    const int r0 = w * 16 + gid;
    const int r1 = r0 + 8;

    // stage s2 chunk (512 values, 256 threads)
    #pragma unroll
    for (int e = 0; e < 2; ++e)
        s2s[t + e * 256] = g_s2[j0 + t + e * 256];

    // stage ALL 8 B tiles (64 KB contiguous from g_hp, L2-resident)
    {
        const uint4* src = reinterpret_cast<const uint4*>(g_hp) + ((size_t)j0 >> 4) * 128;
        #pragma unroll
        for (int k = 0; k < 16; ++k) {
            const int sg = t + k * 256;          // 0..4095
            const uint4 v = __ldg(src + sg);
            const int tile = sg >> 9;
            const int s    = sg & 511;
            *reinterpret_cast<uint4*>(&Bs[tile][s >> 5][(2 * s) & 63]) = v;
        }
    }

    // per-row constants (log2-domain, with overflow-bound m2 folded in)
    const float s2m = fdec(g_s2key);
    float s1a0, s1b0, mc0, s1a1, s1b1, mc1;
    {
        const float s1r = g_s1[i0 + r0];
        const float tt = s1r + s2m;
        const float m2 = fmaxf(fmaxf(tt, 0.2f * tt), NEG10L2E);
        s1a0 = s1r - m2;
        s1b0 = 0.2f * s1r - m2;
        mc0 = NEG10L2E - m2;
    }
    {
        const float s1r = g_s1[i0 + r1];
        const float tt = s1r + s2m;
        const float m2 = fmaxf(fmaxf(tt, 0.2f * tt), NEG10L2E);
        s1a1 = s1r - m2;
        s1b1 = 0.2f * s1r - m2;
        mc1 = NEG10L2E - m2;
    }

    const int4* a0p = reinterpret_cast<const int4*>(
        adj + (size_t)(i0 + r0) * N_NODES + j0) + tig;
    const int4* a1p = reinterpret_cast<const int4*>(
        adj + (size_t)(i0 + r1) * N_NODES + j0) + tig;

    float c[8][4];
    #pragma unroll
    for (int nt = 0; nt < 8; ++nt) {
        c[nt][0] = 0.f; c[nt][1] = 0.f; c[nt][2] = 0.f; c[nt][3] = 0.f;
    }
    float lac0 = 0.f, lac1 = 0.f;

    // prefetch tile 0 adj (latency covered by B staging + barrier wait)
    int4 av0[4], av1[4];
    #pragma unroll
    for (int ks = 0; ks < 4; ++ks) {
        av0[ks] = __ldg(a0p + ks * 4);
        av1[ks] = __ldg(a1p + ks * 4);
    }

    __syncthreads();   // the ONLY barrier: B + s2 staged

    #pragma unroll 1
    for (int tile = 0; tile < NT; ++tile) {
        // rotation target: next tile (last tile harmlessly reloads itself)
        const int nxt = (tile + 1 < NT) ? tile + 1 : tile;

        #pragma unroll
        for (int ks = 0; ks < 4; ++ks) {
            const float4 s4 = *reinterpret_cast<const float4*>(
                s2s + tile * TKJ + ks * 16 + 4 * tig);

            const float w00 = wgt(s1a0, s1b0, mc0, s4.x, av0[ks].x);
            const float w01 = wgt(s1a0, s1b0, mc0, s4.y, av0[ks].y);
            const float w02 = wgt(s1a0, s1b0, mc0, s4.z, av0[ks].z);
            const float w03 = wgt(s1a0, s1b0, mc0, s4.w, av0[ks].w);
            const float w10 = wgt(s1a1, s1b1, mc1, s4.x, av1[ks].x);
            const float w11 = wgt(s1a1, s1b1, mc1, s4.y, av1[ks].y);
            const float w12 = wgt(s1a1, s1b1, mc1, s4.z, av1[ks].z);
            const float w13 = wgt(s1a1, s1b1, mc1, s4.w, av1[ks].w);

            // av[ks] consumed: rotate in next tile's loads (same registers)
            av0[ks] = __ldg(a0p + nxt * 16 + ks * 4);
            av1[ks] = __ldg(a1p + nxt * 16 + ks * 4);

            lac0 += (w00 + w01) + (w02 + w03);
            lac1 += (w10 + w11) + (w12 + w13);

            const uint32_t A0 = packh2(w00, w01);
            const uint32_t A1 = packh2(w10, w11);
            const uint32_t A2 = packh2(w02, w03);
            const uint32_t A3 = packh2(w12, w13);

            const uint2* brow = &Bs[tile][ks * 4 + tig][gid];
            #pragma unroll
            for (int nt = 0; nt < 8; ++nt) {
                const uint2 b = brow[nt * 8];
                mma_fp16(c[nt], A0, A1, A2, A3, b.x, b.y);
            }
        }
    }

    // epilogue: fp16 partials (scaled by 2^-m2 per row — cancels in k_reduce)
    #pragma unroll
    for (int nt = 0; nt < 8; ++nt) {
        const int col = nt * 8 + tig * 2;
        *reinterpret_cast<uint32_t*>(&g_parth[js][i0 + r0][col]) =
            packh2(c[nt][0], c[nt][1]);
        *reinterpret_cast<uint32_t*>(&g_parth[js][i0 + r1][col]) =
            packh2(c[nt][2], c[nt][3]);
    }

    // l partials: reduce across the 4 tig-lanes sharing each row
    lac0 += __shfl_xor_sync(0xffffffffu, lac0, 1);
    lac0 += __shfl_xor_sync(0xffffffffu, lac0, 2);
    lac1 += __shfl_xor_sync(0xffffffffu, lac1, 1);
    lac1 += __shfl_xor_sync(0xffffffffu, lac1, 2);
    if (tig == 0) {
        g_lpart[js][i0 + r0] = lac0;
        g_lpart[js][i0 + r1] = lac1;
    }
}

// ============================================================================
// Kernel 3: reduce 16 fp16 partials, normalize, ELU. 4 cols per thread.
// ============================================================================
__global__ __launch_bounds__(256) void k_reduce(float* __restrict__ out)
{
    const int gi = blockIdx.x * 256 + threadIdx.x;   // over N*16
    const int i = gi >> 4;
    const int f4 = (gi & 15) * 4;

    float4 s = make_float4(0.f, 0.f, 0.f, 0.f);
    float lsum = 0.f;
    #pragma unroll
    for (int p = 0; p < JSPLIT; ++p) {
        const uint2 v = *reinterpret_cast<const uint2*>(&g_parth[p][i][f4]);
        const float2 f0 = __half22float2(*reinterpret_cast<const __half2*>(&v.x));
        const float2 f1 = __half22float2(*reinterpret_cast<const __half2*>(&v.y));
        s.x += f0.x; s.y += f0.y; s.z += f1.x; s.w += f1.y;
        lsum += g_lpart[p][i];
    }
    const float inv = 1.0f / lsum;
    float4 o;
    o.x = s.x * inv; o.y = s.y * inv; o.z = s.z * inv; o.w = s.w * inv;
    o.x = o.x > 0.f ? o.x : (__expf(o.x) - 1.f);
    o.y = o.y > 0.f ? o.y : (__expf(o.y) - 1.f);
    o.z = o.z > 0.f ? o.z : (__expf(o.z) - 1.f);
    o.w = o.w > 0.f ? o.w : (__expf(o.w) - 1.f);
    *reinterpret_cast<float4*>(&out[(size_t)i * FOUT + f4]) = o;
}

// ============================================================================
extern "C" void kernel_launch(void* const* d_in, const int* in_sizes, int n_in,
                              void* d_out, int out_size)
{
    const float* input = (const float*)d_in[0];  // [8192, 256]
    const int*   adj   = (const int*)  d_in[1];  // [8192, 8192]
    const float* W     = (const float*)d_in[2];  // [256, 64]
    const float* a     = (const float*)d_in[3];  // [128, 1]
    float* out = (float*)d_out;                  // [8192, 64]

    cudaFuncSetAttribute(k_mma, cudaFuncAttributeMaxDynamicSharedMemorySize, SMEM_MMA);

    k_h<<<N_NODES / 64, 512>>>(input, W, a);
    k_mma<<<dim3(N_NODES / TM, JSPLIT), 256, SMEM_MMA>>>(adj);
    k_reduce<<<(N_NODES * 16) / 256, 256>>>(out);
}

// round 17
// speedup vs baseline: 1.0925x; 1.0925x over previous
#include <cuda_runtime.h>
#include <cuda_fp16.h>
#include <cstdint>

#define N_NODES 8192
#define FIN 256
#define FOUT 64
#define LOG2E 1.4426950408889634f
#define NEG10L2E (-14.426950408889634f)

// ---- k_mma geometry (R12-proven shape) ----
#define TM 128
#define TKJ 64
#define JSPLIT 16
#define KCHUNK (N_NODES / JSPLIT)    // 512
#define NT (KCHUNK / TKJ)            // 8

// dynamic smem layout for k_mma
#define BS_BYTES (8 * 16 * 68 * 8)         // 69632
#define SMEM_MMA (BS_BYTES + KCHUNK * 4)   // 71680

// ---- scratch (allocation-free rule) ----
__device__ float g_s1[N_NODES];                    // prescaled by LOG2E
__device__ float g_s2[N_NODES];                    // prescaled by LOG2E
__device__ uint2 g_hp[(N_NODES / 16) * 256];       // fragment-packed fp16 h, 1 MB
__device__ __half g_parth[JSPLIT][N_NODES][FOUT];  // fp16 partials, 16 MB
__device__ float g_lpart[JSPLIT][N_NODES];         // 512 KB
__device__ unsigned g_s2key = 0u;                  // ordered-key max of s2' (idempotent)

__device__ __forceinline__ unsigned fenc(float f) {
    unsigned u = __float_as_uint(f);
    return u ^ ((unsigned)((int)u >> 31) | 0x80000000u);
}
__device__ __forceinline__ float fdec(unsigned u) {
    unsigned b = (u & 0x80000000u) ? (u ^ 0x80000000u) : ~u;
    return __uint_as_float(b);
}
__device__ __forceinline__ float ex2(float x) {
    float r;
    asm("ex2.approx.f32 %0, %1;" : "=f"(r) : "f"(x));
    return r;
}
__device__ __forceinline__ uint32_t packh2(float lo, float hi) {
    uint32_t r;
    asm("cvt.rn.f16x2.f32 %0, %1, %2;" : "=r"(r) : "f"(hi), "f"(lo));
    return r;
}
__device__ __forceinline__ void mma_fp16(float c[4],
    uint32_t a0, uint32_t a1, uint32_t a2, uint32_t a3,
    uint32_t b0, uint32_t b1)
{
    asm volatile(
        "mma.sync.aligned.m16n8k16.row.col.f32.f16.f16.f32 "
        "{%0,%1,%2,%3}, {%4,%5,%6,%7}, {%8,%9}, {%0,%1,%2,%3};"
        : "+f"(c[0]), "+f"(c[1]), "+f"(c[2]), "+f"(c[3])
        : "r"(a0), "r"(a1), "r"(a2), "r"(a3), "r"(b0), "r"(b1));
}
// weight in log2 domain: lrelu2 - m2 folded into per-row consts
__device__ __forceinline__ float wgt(float s1a, float s1b, float mc,
                                     float s2, int av) {
    const float t1 = s1a + s2;
    const float t2 = fmaf(0.2f, s2, s1b);
    float y = fmaxf(t1, t2);
    y = (av > 0) ? y : mc;
    return ex2(y);
}

// ============================================================================
// Kernel 1: h = input @ W (64-row tiles, register-prefetched chunks); emit
// prescaled s1,s2, s2'-max, pi-permuted fp16 B. Grid: 128 blocks, 512 thr.
// ============================================================================
__global__ __launch_bounds__(512) void k_h(
    const float* __restrict__ input,   // [N, FIN]
    const float* __restrict__ W,       // [FIN, FOUT]
    const float* __restrict__ a)       // [2*FOUT]
{
    __shared__ float pool[8192];       // in_s[64][64] @0 | w_s[64][64] @4096
    const int t = threadIdx.x;         // 0..511
    const int i0 = blockIdx.x * 64;
    const int f4 = (t & 15) * 4;
    const int i2 = (t >> 4) * 2;       // 2 rows per thread

    const float4* in4 = reinterpret_cast<const float4*>(input);
    const float4* W4  = reinterpret_cast<const float4*>(W);

    float4 pin[2], pw[2];
    const int ldrow0 = t >> 4, ldc0 = t & 15;
    const int ldrow1 = (t + 512) >> 4, ldc1 = (t + 512) & 15;

    pin[0] = in4[(size_t)(i0 + ldrow0) * 64 + ldc0];
    pin[1] = in4[(size_t)(i0 + ldrow1) * 64 + ldc1];
    pw[0]  = W4[(size_t)ldrow0 * 16 + ldc0];
    pw[1]  = W4[(size_t)ldrow1 * 16 + ldc1];

    float c[2][4];
    #pragma unroll
    for (int r = 0; r < 2; ++r) { c[r][0]=0.f; c[r][1]=0.f; c[r][2]=0.f; c[r][3]=0.f; }

    for (int kc = 0; kc < 4; ++kc) {
        __syncthreads();
        *reinterpret_cast<float4*>(&pool[ldrow0 * 64 + ldc0 * 4]) = pin[0];
        *reinterpret_cast<float4*>(&pool[ldrow1 * 64 + ldc1 * 4]) = pin[1];
        *reinterpret_cast<float4*>(&pool[4096 + ldrow0 * 64 + ldc0 * 4]) = pw[0];
        *reinterpret_cast<float4*>(&pool[4096 + ldrow1 * 64 + ldc1 * 4]) = pw[1];
        __syncthreads();

        if (kc < 3) {
            pin[0] = in4[(size_t)(i0 + ldrow0) * 64 + (kc + 1) * 16 + ldc0];
            pin[1] = in4[(size_t)(i0 + ldrow1) * 64 + (kc + 1) * 16 + ldc1];
            pw[0]  = W4[(size_t)((kc + 1) * 64 + ldrow0) * 16 + ldc0];
            pw[1]  = W4[(size_t)((kc + 1) * 64 + ldrow1) * 16 + ldc1];
        }

        #pragma unroll 8
        for (int kk = 0; kk < 64; ++kk) {
            const float4 wv = *reinterpret_cast<const float4*>(&pool[4096 + kk * 64 + f4]);
            #pragma unroll
            for (int r = 0; r < 2; ++r) {
                const float iv = pool[(i2 + r) * 64 + kk];
                c[r][0] = fmaf(iv, wv.x, c[r][0]);
                c[r][1] = fmaf(iv, wv.y, c[r][1]);
                c[r][2] = fmaf(iv, wv.z, c[r][2]);
                c[r][3] = fmaf(iv, wv.w, c[r][3]);
            }
        }
    }

    // stage fp32 h into padded smem h_s[64][65]
    __syncthreads();
    #pragma unroll
    for (int r = 0; r < 2; ++r) {
        float* row = &pool[(i2 + r) * 65 + f4];
        row[0] = c[r][0]; row[1] = c[r][1]; row[2] = c[r][2]; row[3] = c[r][3];
    }
    __syncthreads();

    // s1 / s2 (exact fp32), prescaled by log2(e); chip-wide max of s2'
    if (t < 64) {
        float s1 = 0.f, s2 = 0.f;
        #pragma unroll 8
        for (int f = 0; f < 64; ++f) {
            const float hv = pool[t * 65 + f];
            s1 = fmaf(hv, __ldg(&a[f]), s1);
            s2 = fmaf(hv, __ldg(&a[64 + f]), s2);
        }
        g_s1[i0 + t] = s1 * LOG2E;
        const float s2p = s2 * LOG2E;
        g_s2[i0 + t] = s2p;
        float m = s2p;
        #pragma unroll
        for (int d = 16; d; d >>= 1)
            m = fmaxf(m, __shfl_xor_sync(0xffffffffu, m, d));
        if ((t & 31) == 0) atomicMax(&g_s2key, fenc(m));
    }

    // pi-permuted fragment-packed fp16 h:
    // per 16-row block, entry (q,f): .x=(h[4q],h[4q+1]), .y=(h[4q+2],h[4q+3])
    #pragma unroll
    for (int e = 0; e < 2; ++e) {
        const int idx = t + e * 512;        // 0..1023
        const int blk = idx >> 8;           // 0..3
        const int q   = (idx >> 6) & 3;
        const int f   = idx & 63;
        const int rb  = blk * 16 + 4 * q;
        uint2 v;
        v.x = packh2(pool[(rb + 0) * 65 + f], pool[(rb + 1) * 65 + f]);
        v.y = packh2(pool[(rb + 2) * 65 + f], pool[(rb + 3) * 65 + f]);
        g_hp[((i0 >> 4) + blk) * 256 + q * 64 + f] = v;
    }
}

// ============================================================================
// Kernel 2: fused fp16 HMMA GEMM — EXACT R12 mainloop (whole 8-tile B chunk
// staged once, barrier-free, 8 adj LDG.128 batched at tile top for MLP 8),
// fp16 partial epilogue. Grid (64, 16), 256 thr, occ 2.
// ============================================================================
__global__ __launch_bounds__(256, 2) void k_mma(const int* __restrict__ adj)
{
    extern __shared__ __align__(16) char smem[];
    uint2 (*Bs)[16][68] = reinterpret_cast<uint2 (*)[16][68]>(smem);   // [8][16][68]
    float* s2s = reinterpret_cast<float*>(smem + BS_BYTES);            // [512]

    const int t = threadIdx.x;
    const int w = t >> 5;
    const int l = t & 31;
    const int gid = l >> 2;
    const int tig = l & 3;
    const int i0 = blockIdx.x * TM;
    const int js = blockIdx.y;
    const int j0 = js * KCHUNK;
    const int r0 = w * 16 + gid;
    const int r1 = r0 + 8;

    // stage s2 chunk (512 values, 256 threads)
    #pragma unroll
    for (int e = 0; e < 2; ++e)
        s2s[t + e * 256] = g_s2[j0 + t + e * 256];

    // stage ALL 8 B tiles (64 KB contiguous from g_hp, L2-resident)
    {
        const uint4* src = reinterpret_cast<const uint4*>(g_hp) + ((size_t)j0 >> 4) * 128;
        #pragma unroll
        for (int k = 0; k < 16; ++k) {
            const int sg = t + k * 256;          // 0..4095
            const uint4 v = __ldg(src + sg);
            const int tile = sg >> 9;
            const int s    = sg & 511;
            *reinterpret_cast<uint4*>(&Bs[tile][s >> 5][(2 * s) & 63]) = v;
        }
    }

    // per-row constants (log2-domain, with overflow-bound m2 folded in)
    const float s2m = fdec(g_s2key);
    float s1a0, s1b0, mc0, s1a1, s1b1, mc1;
    {
        const float s1r = g_s1[i0 + r0];
        const float tt = s1r + s2m;
        const float m2 = fmaxf(fmaxf(tt, 0.2f * tt), NEG10L2E);
        s1a0 = s1r - m2;
        s1b0 = 0.2f * s1r - m2;
        mc0 = NEG10L2E - m2;
    }
    {
        const float s1r = g_s1[i0 + r1];
        const float tt = s1r + s2m;
        const float m2 = fmaxf(fmaxf(tt, 0.2f * tt), NEG10L2E);
        s1a1 = s1r - m2;
        s1b1 = 0.2f * s1r - m2;
        mc1 = NEG10L2E - m2;
    }

    const int4* a0p = reinterpret_cast<const int4*>(
        adj + (size_t)(i0 + r0) * N_NODES + j0) + tig;
    const int4* a1p = reinterpret_cast<const int4*>(
        adj + (size_t)(i0 + r1) * N_NODES + j0) + tig;

    float c[8][4];
    #pragma unroll
    for (int nt = 0; nt < 8; ++nt) {
        c[nt][0] = 0.f; c[nt][1] = 0.f; c[nt][2] = 0.f; c[nt][3] = 0.f;
    }
    float lac0 = 0.f, lac1 = 0.f;

    __syncthreads();   // the ONLY barrier: B + s2 staged

    #pragma unroll 1
    for (int tile = 0; tile < NT; ++tile) {
        // adj loads for this tile: 8 LDG.128 batched back-to-back (MLP 8)
        int4 av0[4], av1[4];
        #pragma unroll
        for (int ks = 0; ks < 4; ++ks) {
            av0[ks] = __ldg(a0p + tile * 16 + ks * 4);
            av1[ks] = __ldg(a1p + tile * 16 + ks * 4);
        }

        #pragma unroll
        for (int ks = 0; ks < 4; ++ks) {
            const float4 s4 = *reinterpret_cast<const float4*>(
                s2s + tile * TKJ + ks * 16 + 4 * tig);

            const float w00 = wgt(s1a0, s1b0, mc0, s4.x, av0[ks].x);
            const float w01 = wgt(s1a0, s1b0, mc0, s4.y, av0[ks].y);
            const float w02 = wgt(s1a0, s1b0, mc0, s4.z, av0[ks].z);
            const float w03 = wgt(s1a0, s1b0, mc0, s4.w, av0[ks].w);
            const float w10 = wgt(s1a1, s1b1, mc1, s4.x, av1[ks].x);
            const float w11 = wgt(s1a1, s1b1, mc1, s4.y, av1[ks].y);
            const float w12 = wgt(s1a1, s1b1, mc1, s4.z, av1[ks].z);
            const float w13 = wgt(s1a1, s1b1, mc1, s4.w, av1[ks].w);

            lac0 += (w00 + w01) + (w02 + w03);
            lac1 += (w10 + w11) + (w12 + w13);

            const uint32_t A0 = packh2(w00, w01);
            const uint32_t A1 = packh2(w10, w11);
            const uint32_t A2 = packh2(w02, w03);
            const uint32_t A3 = packh2(w12, w13);

            const uint2* brow = &Bs[tile][ks * 4 + tig][gid];
            #pragma unroll
            for (int nt = 0; nt < 8; ++nt) {
                const uint2 b = brow[nt * 8];
                mma_fp16(c[nt], A0, A1, A2, A3, b.x, b.y);
            }
        }
    }

    // epilogue: fp16 partials (scaled by 2^-m2 per row — cancels in k_reduce)
    #pragma unroll
    for (int nt = 0; nt < 8; ++nt) {
        const int col = nt * 8 + tig * 2;
        *reinterpret_cast<uint32_t*>(&g_parth[js][i0 + r0][col]) =
            packh2(c[nt][0], c[nt][1]);
        *reinterpret_cast<uint32_t*>(&g_parth[js][i0 + r1][col]) =
            packh2(c[nt][2], c[nt][3]);
    }

    // l partials: reduce across the 4 tig-lanes sharing each row
    lac0 += __shfl_xor_sync(0xffffffffu, lac0, 1);
    lac0 += __shfl_xor_sync(0xffffffffu, lac0, 2);
    lac1 += __shfl_xor_sync(0xffffffffu, lac1, 1);
    lac1 += __shfl_xor_sync(0xffffffffu, lac1, 2);
    if (tig == 0) {
        g_lpart[js][i0 + r0] = lac0;
        g_lpart[js][i0 + r1] = lac1;
    }
}

// ============================================================================
// Kernel 3: reduce 16 fp16 partials, normalize, ELU. 4 cols per thread.
// ============================================================================
__global__ __launch_bounds__(256) void k_reduce(float* __restrict__ out)
{
    const int gi = blockIdx.x * 256 + threadIdx.x;   // over N*16
    const int i = gi >> 4;
    const int f4 = (gi & 15) * 4;

    float4 s = make_float4(0.f, 0.f, 0.f, 0.f);
    float lsum = 0.f;
    #pragma unroll
    for (int p = 0; p < JSPLIT; ++p) {
        const uint2 v = *reinterpret_cast<const uint2*>(&g_parth[p][i][f4]);
        const float2 f0 = __half22float2(*reinterpret_cast<const __half2*>(&v.x));
        const float2 f1 = __half22float2(*reinterpret_cast<const __half2*>(&v.y));
        s.x += f0.x; s.y += f0.y; s.z += f1.x; s.w += f1.y;
        lsum += g_lpart[p][i];
    }
    const float inv = 1.0f / lsum;
    float4 o;
    o.x = s.x * inv; o.y = s.y * inv; o.z = s.z * inv; o.w = s.w * inv;
    o.x = o.x > 0.f ? o.x : (__expf(o.x) - 1.f);
    o.y = o.y > 0.f ? o.y : (__expf(o.y) - 1.f);
    o.z = o.z > 0.f ? o.z : (__expf(o.z) - 1.f);
    o.w = o.w > 0.f ? o.w : (__expf(o.w) - 1.f);
    *reinterpret_cast<float4*>(&out[(size_t)i * FOUT + f4]) = o;
}

// ============================================================================
extern "C" void kernel_launch(void* const* d_in, const int* in_sizes, int n_in,
                              void* d_out, int out_size)
{
    const float* input = (const float*)d_in[0];  // [8192, 256]
    const int*   adj   = (const int*)  d_in[1];  // [8192, 8192]
    const float* W     = (const float*)d_in[2];  // [256, 64]
    const float* a     = (const float*)d_in[3];  // [128, 1]
    float* out = (float*)d_out;                  // [8192, 64]

    cudaFuncSetAttribute(k_mma, cudaFuncAttributeMaxDynamicSharedMemorySize, SMEM_MMA);

    k_h<<<N_NODES / 64, 512>>>(input, W, a);
    k_mma<<<dim3(N_NODES / TM, JSPLIT), 256, SMEM_MMA>>>(adj);
    k_reduce<<<(N_NODES * 16) / 256, 256>>>(out);
}